// round 1
// baseline (speedup 1.0000x reference)
#include <cuda_runtime.h>

// StackMemory: the scan degenerates because stack rows 1..31 are never
// written (stack0 = 0, only row 0 is set each step), so s1 == 0 always and
//   out[0, t, 0, h] = softmax(x_t @ W^T + b)[0] * sigmoid(x_t @ D)   (all h)
//   out[0, t, d, h] = 0   for d >= 1
// Pure store-bandwidth problem: 419 MB out, 13 MB in.

#define T_LEN 8192
#define HID   400
#define DEPTH 32
#define NTHREADS 256

__global__ __launch_bounds__(NTHREADS)
void stackmem_kernel(const float* __restrict__ x,   // (T, H)
                     const float* __restrict__ W,   // (3, H)
                     const float* __restrict__ b,   // (3,)
                     const float* __restrict__ D,   // (H,)
                     float* __restrict__ out)       // (T, DEPTH, H)
{
    const int t = blockIdx.x;
    const int tid = threadIdx.x;
    const float* xt = x + (size_t)t * HID;

    // 4 partial dot products
    float s0 = 0.f, s1 = 0.f, s2 = 0.f, sd = 0.f;
    for (int h = tid; h < HID; h += NTHREADS) {
        float v = xt[h];
        s0 = fmaf(v, W[h],           s0);
        s1 = fmaf(v, W[HID + h],     s1);
        s2 = fmaf(v, W[2 * HID + h], s2);
        sd = fmaf(v, D[h],           sd);
    }

    // warp reduce
    #pragma unroll
    for (int off = 16; off > 0; off >>= 1) {
        s0 += __shfl_down_sync(0xffffffffu, s0, off);
        s1 += __shfl_down_sync(0xffffffffu, s1, off);
        s2 += __shfl_down_sync(0xffffffffu, s2, off);
        sd += __shfl_down_sync(0xffffffffu, sd, off);
    }

    __shared__ float red[4][NTHREADS / 32];
    __shared__ float sval;
    const int warp = tid >> 5;
    const int lane = tid & 31;
    if (lane == 0) {
        red[0][warp] = s0;
        red[1][warp] = s1;
        red[2][warp] = s2;
        red[3][warp] = sd;
    }
    __syncthreads();

    if (tid == 0) {
        float l0 = 0.f, l1 = 0.f, l2 = 0.f, ld = 0.f;
        #pragma unroll
        for (int w = 0; w < NTHREADS / 32; w++) {
            l0 += red[0][w];
            l1 += red[1][w];
            l2 += red[2][w];
            ld += red[3][w];
        }
        l0 += b[0]; l1 += b[1]; l2 += b[2];
        // softmax over 3 logits, take index 0 (push)
        float m = fmaxf(l0, fmaxf(l1, l2));
        float e0 = __expf(l0 - m);
        float e1 = __expf(l1 - m);
        float e2 = __expf(l2 - m);
        float push = e0 / (e0 + e1 + e2);
        // sigmoid
        float pv = 1.0f / (1.0f + __expf(-ld));
        sval = push * pv;
    }
    __syncthreads();

    const float v = sval;
    const float4 val4  = make_float4(v, v, v, v);
    const float4 zero4 = make_float4(0.f, 0.f, 0.f, 0.f);

    // Each t owns DEPTH*HID = 12800 floats = 3200 float4 (base 16B aligned:
    // t * 12800 * 4 = t * 51200 bytes). First 100 float4 (d=0 row) = value,
    // the rest zero.
    float4* o = reinterpret_cast<float4*>(out + (size_t)t * DEPTH * HID);
    const int NVEC = DEPTH * HID / 4;       // 3200
    const int NVAL = HID / 4;               // 100
    for (int i = tid; i < NVEC; i += NTHREADS) {
        o[i] = (i < NVAL) ? val4 : zero4;
    }
}

extern "C" void kernel_launch(void* const* d_in, const int* in_sizes, int n_in,
                              void* d_out, int out_size) {
    const float* x = (const float*)d_in[0];   // hidden_state (1, 8192, 400)
    const float* W = (const float*)d_in[1];   // W_ap (3, 400)
    const float* b = (const float*)d_in[2];   // b_ap (3,)
    const float* D = (const float*)d_in[3];   // D (1, 400)
    float* out = (float*)d_out;               // (1, 8192, 32, 400)

    stackmem_kernel<<<T_LEN, NTHREADS>>>(x, W, b, D, out);
}